// round 7
// baseline (speedup 1.0000x reference)
#include <cuda_runtime.h>
#include <cuda_bf16.h>
#include <cstdint>
#include <math.h>

#define DIM    256
#define HEADS  8
#define HD     32
#define N1V    256
#define N2V    256
#define BTOT   256
#define NWIN   128
#define TBL    1575
#define MTOT   (BTOT * N1V)

typedef unsigned long long ull;

// ---------------- scratch (device globals; no allocation) ----------------
__device__ float d_qh [MTOT * DIM];              // scaled Q proj
__device__ float d_kvh[MTOT * 2 * DIM];          // K|V proj
__device__ float d_x  [MTOT * DIM];              // attention output
__device__ float d_biasF[HEADS * N1V * N2V];     // expanded rel-pos bias (2MB)

// ---------------- packed f32x2 helpers (sm_100+ base PTX) ----------------
__device__ __forceinline__ ull pack2(float x, float y) {
    ull r; asm("mov.b64 %0, {%1, %2};" : "=l"(r) : "f"(x), "f"(y)); return r;
}
__device__ __forceinline__ void unpack2(ull v, float& x, float& y) {
    asm("mov.b64 {%0, %1}, %2;" : "=f"(x), "=f"(y) : "l"(v));
}
__device__ __forceinline__ void ffma2(ull& d, ull a, ull b) {
    asm("fma.rn.f32x2 %0, %1, %2, %0;" : "+l"(d) : "l"(a), "l"(b));
}

// ---------------- FFMA2 NT SGEMM: C = alpha * (A @ B^T + bias) -------------
__global__ void __launch_bounds__(256) gemm_nt(
    const float* __restrict__ A, const float* __restrict__ B,
    const float* __restrict__ bias, float* __restrict__ C,
    int M, int N, int K, float alpha)
{
    __shared__ float As[16][132];
    __shared__ float Bs[16][132];
    const int m0  = blockIdx.y * 128;
    const int n0  = blockIdx.x * 128;
    const int tid = threadIdx.x;
    const int tr  = tid >> 4;
    const int tc  = tid & 15;

    ull acc2[8][4];
#pragma unroll
    for (int i = 0; i < 8; i++)
#pragma unroll
        for (int j = 0; j < 4; j++) acc2[i][j] = 0ull;

    for (int k0 = 0; k0 < K; k0 += 16) {
#pragma unroll
        for (int i = 0; i < 2; i++) {
            int li = tid + i * 256;
            int r  = li >> 2;
            int cq = (li & 3) << 2;
            float4 va = *(const float4*)(A + (size_t)(m0 + r) * K + k0 + cq);
            As[cq + 0][r] = va.x; As[cq + 1][r] = va.y;
            As[cq + 2][r] = va.z; As[cq + 3][r] = va.w;
            float4 vb = *(const float4*)(B + (size_t)(n0 + r) * K + k0 + cq);
            Bs[cq + 0][r] = vb.x; Bs[cq + 1][r] = vb.y;
            Bs[cq + 2][r] = vb.z; Bs[cq + 3][r] = vb.w;
        }
        __syncthreads();
#pragma unroll
        for (int kk = 0; kk < 16; kk++) {
            float4 a0 = *(const float4*)&As[kk][tr * 8];
            float4 a1 = *(const float4*)&As[kk][tr * 8 + 4];
            ull b2[4];
#pragma unroll
            for (int j = 0; j < 4; j++)
                b2[j] = *(const ull*)&Bs[kk][tc * 8 + 2 * j];
            ull ad[8];
            ad[0] = pack2(a0.x, a0.x); ad[1] = pack2(a0.y, a0.y);
            ad[2] = pack2(a0.z, a0.z); ad[3] = pack2(a0.w, a0.w);
            ad[4] = pack2(a1.x, a1.x); ad[5] = pack2(a1.y, a1.y);
            ad[6] = pack2(a1.z, a1.z); ad[7] = pack2(a1.w, a1.w);
#pragma unroll
            for (int i = 0; i < 8; i++)
#pragma unroll
                for (int j = 0; j < 4; j++)
                    ffma2(acc2[i][j], ad[i], b2[j]);
        }
        __syncthreads();
    }

#pragma unroll
    for (int i = 0; i < 8; i++) {
        int r = m0 + tr * 8 + i;
#pragma unroll
        for (int j = 0; j < 4; j++) {
            int c = n0 + tc * 8 + 2 * j;
            float x, y;
            unpack2(acc2[i][j], x, y);
            float2 v;
            v.x = alpha * (x + bias[c]);
            v.y = alpha * (y + bias[c + 1]);
            *(float2*)(C + (size_t)r * N + c) = v;
        }
    }
}

// ---------------- rel-pos bias expansion: biasF[h][q][k] -------------------
__global__ void __launch_bounds__(256) bias_pre(
    const float* __restrict__ btab_g, const int* __restrict__ rel,
    float* __restrict__ biasF)
{
    int idx = blockIdx.x * 256 + threadIdx.x;     // over N1*N2 = 65536
    int ri  = rel[idx] * HEADS;
#pragma unroll
    for (int h = 0; h < HEADS; h++)
        biasF[h * (N1V * N2V) + idx] = btab_g[ri + h];
}

// ---------------- attention kernel v2 --------------------------------------
// grid (4 qtiles, HEADS, BTOT), 512 threads.
// tx = tid>>3 (query 0..63), ty = tid&7 (key group; keys j = 8*jj + ty).
// ty sits in lane bits 0..2 -> softmax / O reductions via shfl.bfly 1,2,4.
struct __align__(16) AttnSmem2 {
    union U {
        float KV[256][36];        // K tile, then V tile (36864 B)
        float stage[64][68];      // mask+bias chunk   (17408 B)
    } u;
    float Qs[64][34];             // 8704 B
};

__global__ void __launch_bounds__(512) attn_kernel(
    const float* __restrict__ qh, const float* __restrict__ kvh,
    const float* __restrict__ mask, const float* __restrict__ biasF,
    float* __restrict__ xout)
{
    __shared__ AttnSmem2 sm;
    const int tid = threadIdx.x;
    const int tx  = tid >> 3;
    const int ty  = tid & 7;
    const int q0  = blockIdx.x * 64;
    const int h   = blockIdx.y;
    const int b   = blockIdx.z;
    const int w   = b & (NWIN - 1);

    // ---- load Q (64x32) and K (256x32) ----
    {
        const float* qbase = qh + ((size_t)(b * N1V + q0)) * DIM + h * HD;
#pragma unroll
        for (int i = 0; i < 2; i++) {
            int li = tid + i * 512;          // 0..1023 float2 slots
            int r  = li >> 4;
            int c2 = (li & 15) * 2;
            float2 v = *(const float2*)(qbase + (size_t)r * DIM + c2);
            *(float2*)&sm.Qs[r][c2] = v;     // 34-stride: 8B aligned
        }
        const float* kbase = kvh + ((size_t)b * N2V) * (2 * DIM) + h * HD;
#pragma unroll
        for (int i = 0; i < 4; i++) {
            int li = tid + i * 512;          // 0..2047 float4 slots
            int r  = li >> 3;
            int c4 = (li & 7) * 4;
            float4 v = *(const float4*)(kbase + (size_t)r * (2 * DIM) + c4);
            *(float4*)&sm.u.KV[r][c4] = v;   // 36-stride: 16B aligned
        }
    }
    __syncthreads();

    // ---- QK: 32 keys per thread (j = 8*jj + ty) ----
    ull qp[16];
#pragma unroll
    for (int c = 0; c < 16; c++) qp[c] = *(const ull*)&sm.Qs[tx][2 * c];

    float s[32];
#pragma unroll
    for (int jj = 0; jj < 32; jj++) {
        const float* kr = sm.u.KV[8 * jj + ty];
        ull acc = 0ull;
#pragma unroll
        for (int c = 0; c < 8; c++) {
            ulonglong2 v = *(const ulonglong2*)&kr[4 * c];
            ffma2(acc, qp[2 * c],     v.x);
            ffma2(acc, qp[2 * c + 1], v.y);
        }
        float x, y;
        unpack2(acc, x, y);
        s[jj] = x + y;
    }
    __syncthreads();   // done reading K; KV region now reusable for staging

    // ---- mask + bias, staged per 64-col chunk (all threads active) ----
    const float* maskb = mask  + ((size_t)(w * N1V + q0)) * N2V;
    const float* biasb = biasF + ((size_t)(h * N1V + q0)) * N2V;
#pragma unroll 1
    for (int ch = 0; ch < 4; ch++) {
#pragma unroll
        for (int i = 0; i < 2; i++) {
            int li = tid + i * 512;          // 0..1023 float4 slots (64x64/4)
            int r  = li >> 4;
            int c4 = (li & 15) * 4;
            float4 mv = *(const float4*)(maskb + (size_t)r * N2V + ch * 64 + c4);
            float4 bv = *(const float4*)(biasb + (size_t)r * N2V + ch * 64 + c4);
            float4 sv;
            sv.x = mv.x + bv.x; sv.y = mv.y + bv.y;
            sv.z = mv.z + bv.z; sv.w = mv.w + bv.w;
            *(float4*)&sm.u.stage[r][c4] = sv;   // 68-stride: 16B aligned
        }
        __syncthreads();
#pragma unroll
        for (int i = 0; i < 8; i++)          // key j = ch*64 + 8i + ty -> jj = ch*8+i
            s[ch * 8 + i] += sm.u.stage[tx][8 * i + ty];
        __syncthreads();
    }

    // ---- softmax over 256 keys: per-thread 32 + bfly over 8 ty lanes ----
    float mx = -1e30f;
#pragma unroll
    for (int jj = 0; jj < 32; jj++) mx = fmaxf(mx, s[jj]);
    mx = fmaxf(mx, __shfl_xor_sync(0xFFFFFFFFu, mx, 1));
    mx = fmaxf(mx, __shfl_xor_sync(0xFFFFFFFFu, mx, 2));
    mx = fmaxf(mx, __shfl_xor_sync(0xFFFFFFFFu, mx, 4));
    float lsum = 0.f;
#pragma unroll
    for (int jj = 0; jj < 32; jj++) {
        float e = __expf(s[jj] - mx);
        s[jj] = e;
        lsum += e;
    }
    lsum += __shfl_xor_sync(0xFFFFFFFFu, lsum, 1);
    lsum += __shfl_xor_sync(0xFFFFFFFFu, lsum, 2);
    lsum += __shfl_xor_sync(0xFFFFFFFFu, lsum, 4);
    const float linv = 1.0f / lsum;

    // ---- load V into KV region ----
    {
        const float* vbase = kvh + ((size_t)b * N2V) * (2 * DIM) + DIM + h * HD;
#pragma unroll
        for (int i = 0; i < 4; i++) {
            int li = tid + i * 512;
            int r  = li >> 3;
            int c4 = (li & 7) * 4;
            float4 v = *(const float4*)(vbase + (size_t)r * (2 * DIM) + c4);
            *(float4*)&sm.u.KV[r][c4] = v;
        }
    }
    __syncthreads();

    // ---- PV: accumulate this thread's 32 keys over all 32 dims ----
    ull o2[16];
#pragma unroll
    for (int d = 0; d < 16; d++) o2[d] = 0ull;
#pragma unroll
    for (int jj = 0; jj < 32; jj++) {
        ull pp = pack2(s[jj], s[jj]);
        const float* vr = sm.u.KV[8 * jj + ty];
#pragma unroll
        for (int c = 0; c < 8; c++) {
            ulonglong2 v = *(const ulonglong2*)&vr[4 * c];
            ffma2(o2[2 * c],     pp, v.x);
            ffma2(o2[2 * c + 1], pp, v.y);
        }
    }

    // ---- O reduction across the 8 ty lanes via bfly shuffles ----
    float o[32];
#pragma unroll
    for (int d = 0; d < 16; d++) unpack2(o2[d], o[2 * d], o[2 * d + 1]);
#pragma unroll
    for (int st = 1; st <= 4; st <<= 1) {
#pragma unroll
        for (int d = 0; d < 32; d++)
            o[d] += __shfl_xor_sync(0xFFFFFFFFu, o[d], st);
    }

    // ---- write: thread (tx,ty) writes dims [4*ty .. 4*ty+3] ----
    {
        float4 v;
        v.x = o[4 * ty]     * linv;
        v.y = o[4 * ty + 1] * linv;
        v.z = o[4 * ty + 2] * linv;
        v.w = o[4 * ty + 3] * linv;
        *(float4*)(xout + ((size_t)(b * N1V + q0 + tx)) * DIM + h * HD + 4 * ty) = v;
    }
}

// ---------------- launch ----------------
extern "C" void kernel_launch(void* const* d_in, const int* in_sizes, int n_in,
                              void* d_out, int out_size)
{
    const float* q    = (const float*)d_in[0];
    const float* kv   = (const float*)d_in[1];
    const float* mask = (const float*)d_in[2];
    const float* Wq   = (const float*)d_in[3];
    const float* bq   = (const float*)d_in[4];
    const float* Wkv  = (const float*)d_in[5];
    const float* bkv  = (const float*)d_in[6];
    const float* btab = (const float*)d_in[7];
    const float* Wp   = (const float*)d_in[8];
    const float* bp   = (const float*)d_in[9];
    const int*   rel  = (const int*)d_in[10];
    float* out = (float*)d_out;

    static float* qh  = nullptr;
    static float* kvh = nullptr;
    static float* xb  = nullptr;
    static float* bF  = nullptr;
    if (!qh) {
        cudaGetSymbolAddress((void**)&qh,  d_qh);
        cudaGetSymbolAddress((void**)&kvh, d_kvh);
        cudaGetSymbolAddress((void**)&xb,  d_x);
        cudaGetSymbolAddress((void**)&bF,  d_biasF);
    }

    const int M = MTOT;
    const float scale = 0.17677669529663687f;       // 1/sqrt(32)

    // bias expansion (independent of GEMMs)
    bias_pre<<<N1V * N2V / 256, 256>>>(btab, rel, bF);
    // 1) qh = scale * (q @ Wq^T + bq)
    gemm_nt<<<dim3(DIM / 128, M / 128), 256>>>(q, Wq, bq, qh, M, DIM, DIM, scale);
    // 2) kvh = kv @ Wkv^T + bkv
    gemm_nt<<<dim3((2 * DIM) / 128, M / 128), 256>>>(kv, Wkv, bkv, kvh, M, 2 * DIM, DIM, 1.f);
    // 3) windowed attention
    attn_kernel<<<dim3(4, HEADS, BTOT), 512>>>(qh, kvh, mask, bF, xb);
    // 4) out = x @ Wp^T + bp
    gemm_nt<<<dim3(DIM / 128, M / 128), 256>>>(xb, Wp, bp, out, M, DIM, DIM, 1.f);
}

// round 9
// speedup vs baseline: 1.3944x; 1.3944x over previous
#include <cuda_runtime.h>
#include <cuda_bf16.h>
#include <cstdint>
#include <math.h>

#define DIM    256
#define HEADS  8
#define HD     32
#define N1V    256
#define N2V    256
#define BTOT   256
#define NWIN   128
#define TBL    1575
#define MTOT   (BTOT * N1V)

typedef unsigned long long ull;

// ---------------- scratch (device globals; no allocation) ----------------
__device__ float d_qh [MTOT * DIM];              // scaled Q proj
__device__ float d_kvh[MTOT * 2 * DIM];          // K|V proj
__device__ float d_x  [MTOT * DIM];              // attention output
__device__ float d_biasF[HEADS * N1V * N2V];     // expanded rel-pos bias (2MB)

// ---------------- packed f32x2 helpers ----------------
__device__ __forceinline__ ull pack2(float x, float y) {
    ull r; asm("mov.b64 %0, {%1, %2};" : "=l"(r) : "f"(x), "f"(y)); return r;
}
__device__ __forceinline__ void unpack2(ull v, float& x, float& y) {
    asm("mov.b64 {%0, %1}, %2;" : "=f"(x), "=f"(y) : "l"(v));
}
__device__ __forceinline__ void ffma2(ull& d, ull a, ull b) {
    asm("fma.rn.f32x2 %0, %1, %2, %0;" : "+l"(d) : "l"(a), "l"(b));
}

// ---------------- FFMA2 NT SGEMM: C = alpha * (A @ B^T + bias) -------------
__global__ void __launch_bounds__(256) gemm_nt(
    const float* __restrict__ A, const float* __restrict__ B,
    const float* __restrict__ bias, float* __restrict__ C,
    int M, int N, int K, float alpha)
{
    __shared__ float As[16][132];
    __shared__ float Bs[16][132];
    const int m0  = blockIdx.y * 128;
    const int n0  = blockIdx.x * 128;
    const int tid = threadIdx.x;
    const int tr  = tid >> 4;
    const int tc  = tid & 15;

    ull acc2[8][4];
#pragma unroll
    for (int i = 0; i < 8; i++)
#pragma unroll
        for (int j = 0; j < 4; j++) acc2[i][j] = 0ull;

    for (int k0 = 0; k0 < K; k0 += 16) {
#pragma unroll
        for (int i = 0; i < 2; i++) {
            int li = tid + i * 256;
            int r  = li >> 2;
            int cq = (li & 3) << 2;
            float4 va = *(const float4*)(A + (size_t)(m0 + r) * K + k0 + cq);
            As[cq + 0][r] = va.x; As[cq + 1][r] = va.y;
            As[cq + 2][r] = va.z; As[cq + 3][r] = va.w;
            float4 vb = *(const float4*)(B + (size_t)(n0 + r) * K + k0 + cq);
            Bs[cq + 0][r] = vb.x; Bs[cq + 1][r] = vb.y;
            Bs[cq + 2][r] = vb.z; Bs[cq + 3][r] = vb.w;
        }
        __syncthreads();
#pragma unroll
        for (int kk = 0; kk < 16; kk++) {
            float4 a0 = *(const float4*)&As[kk][tr * 8];
            float4 a1 = *(const float4*)&As[kk][tr * 8 + 4];
            ull b2[4];
#pragma unroll
            for (int j = 0; j < 4; j++)
                b2[j] = *(const ull*)&Bs[kk][tc * 8 + 2 * j];
            ull ad[8];
            ad[0] = pack2(a0.x, a0.x); ad[1] = pack2(a0.y, a0.y);
            ad[2] = pack2(a0.z, a0.z); ad[3] = pack2(a0.w, a0.w);
            ad[4] = pack2(a1.x, a1.x); ad[5] = pack2(a1.y, a1.y);
            ad[6] = pack2(a1.z, a1.z); ad[7] = pack2(a1.w, a1.w);
#pragma unroll
            for (int i = 0; i < 8; i++)
#pragma unroll
                for (int j = 0; j < 4; j++)
                    ffma2(acc2[i][j], ad[i], b2[j]);
        }
        __syncthreads();
    }

#pragma unroll
    for (int i = 0; i < 8; i++) {
        int r = m0 + tr * 8 + i;
#pragma unroll
        for (int j = 0; j < 4; j++) {
            int c = n0 + tc * 8 + 2 * j;
            float x, y;
            unpack2(acc2[i][j], x, y);
            float2 v;
            v.x = alpha * (x + bias[c]);
            v.y = alpha * (y + bias[c + 1]);
            *(float2*)(C + (size_t)r * N + c) = v;
        }
    }
}

// ---------------- rel-pos bias expansion: biasF[h][q][k] -------------------
__global__ void __launch_bounds__(256) bias_pre(
    const float* __restrict__ btab_g, const int* __restrict__ rel,
    float* __restrict__ biasF)
{
    int idx = blockIdx.x * 256 + threadIdx.x;
    int ri  = rel[idx] * HEADS;
#pragma unroll
    for (int h = 0; h < HEADS; h++)
        biasF[h * (N1V * N2V) + idx] = btab_g[ri + h];
}

// ---------------- attention v3: register-tiled -----------------------------
// 256 threads; qg=tid>>4 (4 queries 4qg+i), kg=tid&15 (16 keys kj=16j+kg).
// Dynamic smem: Qs[64][36] | KV[256][36] | Pb[64][260] (stage+P alias).
#define SQ 36      // multiple of 4 -> float4 row accesses stay 16B-aligned
#define SK 36
#define SP 260
#define QS_OFF 0
#define KV_OFF (64 * SQ)                  // 2304 floats
#define PB_OFF (KV_OFF + 256 * SK)        // 11520 floats
#define ATTN_SMEM_BYTES ((PB_OFF + 64 * SP) * 4)   // 112640 B

__global__ void __launch_bounds__(256) attn_kernel(
    const float* __restrict__ qh, const float* __restrict__ kvh,
    const float* __restrict__ mask, const float* __restrict__ biasF,
    float* __restrict__ xout)
{
    extern __shared__ float smem[];
    float* Qs = smem + QS_OFF;
    float* Ks = smem + KV_OFF;     // K tile, later V tile
    float* Pb = smem + PB_OFF;     // mask+bias stage, later P

    const int tid = threadIdx.x;
    const int qg  = tid >> 4;      // 0..15
    const int kg  = tid & 15;      // 0..15
    const int q0  = blockIdx.x * 64;
    const int h   = blockIdx.y;
    const int b   = blockIdx.z;
    const int w   = b & (NWIN - 1);
    const int qi0 = qg * 4;

    // ---- load Q (64x32) and K (256x32) ----
    {
        const float* qbase = qh + ((size_t)(b * N1V + q0)) * DIM + h * HD;
#pragma unroll
        for (int i = 0; i < 2; i++) {
            int li = tid + i * 256;          // 0..511 float4
            int r  = li >> 3;
            int c4 = (li & 7) * 4;
            *(float4*)&Qs[r * SQ + c4] =
                *(const float4*)(qbase + (size_t)r * DIM + c4);
        }
        const float* kbase = kvh + ((size_t)b * N2V) * (2 * DIM) + h * HD;
#pragma unroll
        for (int i = 0; i < 8; i++) {
            int li = tid + i * 256;          // 0..2047 float4
            int r  = li >> 3;
            int c4 = (li & 7) * 4;
            *(float4*)&Ks[r * SK + c4] =
                *(const float4*)(kbase + (size_t)r * (2 * DIM) + c4);
        }
    }
    __syncthreads();

    // ---- QK: s[4 queries][16 keys], 64 independent FMA chains ----
    float s[4][16];
#pragma unroll
    for (int i = 0; i < 4; i++)
#pragma unroll
        for (int j = 0; j < 16; j++) s[i][j] = 0.f;

#pragma unroll 2
    for (int c4 = 0; c4 < 8; c4++) {
        float q[4][4];
#pragma unroll
        for (int i = 0; i < 4; i++) {
            float4 v = *(const float4*)&Qs[(qi0 + i) * SQ + c4 * 4];
            q[i][0] = v.x; q[i][1] = v.y; q[i][2] = v.z; q[i][3] = v.w;
        }
#pragma unroll
        for (int j = 0; j < 16; j++) {
            float4 kv = *(const float4*)&Ks[(16 * j + kg) * SK + c4 * 4];
#pragma unroll
            for (int i = 0; i < 4; i++) {
                s[i][j] = fmaf(q[i][0], kv.x, s[i][j]);
                s[i][j] = fmaf(q[i][1], kv.y, s[i][j]);
                s[i][j] = fmaf(q[i][2], kv.z, s[i][j]);
                s[i][j] = fmaf(q[i][3], kv.w, s[i][j]);
            }
        }
    }
    __syncthreads();   // K reads done -> V may overwrite; Pb free for stage

    // ---- load V (over K) and mask+bias stage (into Pb) ----
    {
        const float* vbase = kvh + ((size_t)b * N2V) * (2 * DIM) + DIM + h * HD;
#pragma unroll
        for (int i = 0; i < 8; i++) {
            int li = tid + i * 256;
            int r  = li >> 3;
            int c4 = (li & 7) * 4;
            *(float4*)&Ks[r * SK + c4] =
                *(const float4*)(vbase + (size_t)r * (2 * DIM) + c4);
        }
        const float* maskb = mask  + ((size_t)(w * N1V + q0)) * N2V;
        const float* biasb = biasF + ((size_t)(h * N1V + q0)) * N2V;
#pragma unroll
        for (int i = 0; i < 16; i++) {
            int li = tid + i * 256;          // 0..4095 float4 (64x256/4)
            int r  = li >> 6;
            int c4 = (li & 63) * 4;
            float4 mv = *(const float4*)(maskb + (size_t)r * N2V + c4);
            float4 bv = *(const float4*)(biasb + (size_t)r * N2V + c4);
            float4 sv;
            sv.x = mv.x + bv.x; sv.y = mv.y + bv.y;
            sv.z = mv.z + bv.z; sv.w = mv.w + bv.w;
            *(float4*)&Pb[r * SP + c4] = sv;
        }
    }
    __syncthreads();

    // ---- add mask+bias; softmax via bfly over kg lane bits ----
#pragma unroll
    for (int i = 0; i < 4; i++)
#pragma unroll
        for (int j = 0; j < 16; j++)
            s[i][j] += Pb[(qi0 + i) * SP + 16 * j + kg];

    float linv[4];
#pragma unroll
    for (int i = 0; i < 4; i++) {
        float mx = s[i][0];
#pragma unroll
        for (int j = 1; j < 16; j++) mx = fmaxf(mx, s[i][j]);
        mx = fmaxf(mx, __shfl_xor_sync(0xFFFFFFFFu, mx, 1));
        mx = fmaxf(mx, __shfl_xor_sync(0xFFFFFFFFu, mx, 2));
        mx = fmaxf(mx, __shfl_xor_sync(0xFFFFFFFFu, mx, 4));
        mx = fmaxf(mx, __shfl_xor_sync(0xFFFFFFFFu, mx, 8));
        float ls = 0.f;
#pragma unroll
        for (int j = 0; j < 16; j++) {
            float e = __expf(s[i][j] - mx);
            s[i][j] = e;
            ls += e;
        }
        ls += __shfl_xor_sync(0xFFFFFFFFu, ls, 1);
        ls += __shfl_xor_sync(0xFFFFFFFFu, ls, 2);
        ls += __shfl_xor_sync(0xFFFFFFFFu, ls, 4);
        ls += __shfl_xor_sync(0xFFFFFFFFu, ls, 8);
        linv[i] = 1.0f / ls;
    }
    __syncthreads();   // stage reads done -> safe to overwrite Pb with P

    // ---- store P = softmax probs (1/l folded) ----
#pragma unroll
    for (int i = 0; i < 4; i++)
#pragma unroll
        for (int j = 0; j < 16; j++)
            Pb[(qi0 + i) * SP + 16 * j + kg] = s[i][j] * linv[i];
    __syncthreads();

    // ---- PV: thread (qg, kg) -> 4 queries x dims {2kg, 2kg+1} ----
    float o[4][2];
#pragma unroll
    for (int i = 0; i < 4; i++) { o[i][0] = 0.f; o[i][1] = 0.f; }

#pragma unroll 4
    for (int k4 = 0; k4 < 64; k4++) {
        float p[4][4];
#pragma unroll
        for (int i = 0; i < 4; i++) {
            float4 v = *(const float4*)&Pb[(qi0 + i) * SP + k4 * 4];
            p[i][0] = v.x; p[i][1] = v.y; p[i][2] = v.z; p[i][3] = v.w;
        }
#pragma unroll
        for (int kk = 0; kk < 4; kk++) {
            float2 vv = *(const float2*)&Ks[(k4 * 4 + kk) * SK + 2 * kg];
#pragma unroll
            for (int i = 0; i < 4; i++) {
                o[i][0] = fmaf(p[i][kk], vv.x, o[i][0]);
                o[i][1] = fmaf(p[i][kk], vv.y, o[i][1]);
            }
        }
    }

    // ---- write O: thread covers (4 queries) x (2 dims) ----
#pragma unroll
    for (int i = 0; i < 4; i++) {
        float2 v; v.x = o[i][0]; v.y = o[i][1];
        *(float2*)(xout + ((size_t)(b * N1V + q0 + qi0 + i)) * DIM
                   + h * HD + 2 * kg) = v;
    }
}

// ---------------- launch ----------------
extern "C" void kernel_launch(void* const* d_in, const int* in_sizes, int n_in,
                              void* d_out, int out_size)
{
    const float* q    = (const float*)d_in[0];
    const float* kv   = (const float*)d_in[1];
    const float* mask = (const float*)d_in[2];
    const float* Wq   = (const float*)d_in[3];
    const float* bq   = (const float*)d_in[4];
    const float* Wkv  = (const float*)d_in[5];
    const float* bkv  = (const float*)d_in[6];
    const float* btab = (const float*)d_in[7];
    const float* Wp   = (const float*)d_in[8];
    const float* bp   = (const float*)d_in[9];
    const int*   rel  = (const int*)d_in[10];
    float* out = (float*)d_out;

    static float* qh  = nullptr;
    static float* kvh = nullptr;
    static float* xb  = nullptr;
    static float* bF  = nullptr;
    if (!qh) {
        cudaGetSymbolAddress((void**)&qh,  d_qh);
        cudaGetSymbolAddress((void**)&kvh, d_kvh);
        cudaGetSymbolAddress((void**)&xb,  d_x);
        cudaGetSymbolAddress((void**)&bF,  d_biasF);
        cudaFuncSetAttribute(attn_kernel,
                             cudaFuncAttributeMaxDynamicSharedMemorySize,
                             ATTN_SMEM_BYTES);
    }

    const int M = MTOT;
    const float scale = 0.17677669529663687f;       // 1/sqrt(32)

    bias_pre<<<N1V * N2V / 256, 256>>>(btab, rel, bF);
    gemm_nt<<<dim3(DIM / 128, M / 128), 256>>>(q, Wq, bq, qh, M, DIM, DIM, scale);
    gemm_nt<<<dim3((2 * DIM) / 128, M / 128), 256>>>(kv, Wkv, bkv, kvh, M, 2 * DIM, DIM, 1.f);
    attn_kernel<<<dim3(4, HEADS, BTOT), 256, ATTN_SMEM_BYTES>>>(qh, kvh, mask, bF, xb);
    gemm_nt<<<dim3(DIM / 128, M / 128), 256>>>(xb, Wp, bp, out, M, DIM, DIM, 1.f);
}

// round 10
// speedup vs baseline: 1.4809x; 1.0620x over previous
#include <cuda_runtime.h>
#include <cuda_bf16.h>
#include <cstdint>
#include <math.h>

#define DIM    256
#define HEADS  8
#define HD     32
#define N1V    256
#define N2V    256
#define BTOT   256
#define NWIN   128
#define TBL    1575
#define MTOT   (BTOT * N1V)

typedef unsigned long long ull;

// ---------------- scratch (device globals; no allocation) ----------------
__device__ float d_qh [MTOT * DIM];              // scaled Q proj
__device__ float d_kvh[MTOT * 2 * DIM];          // K|V proj
__device__ float d_x  [MTOT * DIM];              // attention output
__device__ float d_biasF[HEADS * N1V * N2V];     // expanded rel-pos bias (2MB)

// ---------------- packed f32x2 helpers ----------------
__device__ __forceinline__ ull pack2(float x, float y) {
    ull r; asm("mov.b64 %0, {%1, %2};" : "=l"(r) : "f"(x), "f"(y)); return r;
}
__device__ __forceinline__ void unpack2(ull v, float& x, float& y) {
    asm("mov.b64 {%0, %1}, %2;" : "=f"(x), "=f"(y) : "l"(v));
}
__device__ __forceinline__ void ffma2(ull& d, ull a, ull b) {
    asm("fma.rn.f32x2 %0, %1, %2, %0;" : "+l"(d) : "l"(a), "l"(b));
}

// ---------------- FFMA2 NT SGEMM, double-buffered smem ---------------------
// C = alpha * (A @ B^T + bias); A:[M,K], B:[N,K] row-major.
// block 128x128, k-tile 16, 256 threads, 8x8/thread, 1 barrier per k-tile.
__global__ void __launch_bounds__(256) gemm_nt(
    const float* __restrict__ A, const float* __restrict__ B,
    const float* __restrict__ bias, float* __restrict__ C,
    int M, int N, int K, float alpha)
{
    __shared__ float As[2][16][132];
    __shared__ float Bs[2][16][132];
    const int m0  = blockIdx.y * 128;
    const int n0  = blockIdx.x * 128;
    const int tid = threadIdx.x;
    const int tr  = tid >> 4;
    const int tc  = tid & 15;

    // per-thread staging coords (2 float4 slots each for A and B)
    int lr[2], lc[2];
#pragma unroll
    for (int i = 0; i < 2; i++) {
        int li = tid + i * 256;
        lr[i] = li >> 2;
        lc[i] = (li & 3) << 2;
    }

    ull acc2[8][4];
#pragma unroll
    for (int i = 0; i < 8; i++)
#pragma unroll
        for (int j = 0; j < 4; j++) acc2[i][j] = 0ull;

    const int NT = K >> 4;

    // prologue: tile 0
#pragma unroll
    for (int i = 0; i < 2; i++) {
        float4 va = *(const float4*)(A + (size_t)(m0 + lr[i]) * K + lc[i]);
        As[0][lc[i] + 0][lr[i]] = va.x; As[0][lc[i] + 1][lr[i]] = va.y;
        As[0][lc[i] + 2][lr[i]] = va.z; As[0][lc[i] + 3][lr[i]] = va.w;
        float4 vb = *(const float4*)(B + (size_t)(n0 + lr[i]) * K + lc[i]);
        Bs[0][lc[i] + 0][lr[i]] = vb.x; Bs[0][lc[i] + 1][lr[i]] = vb.y;
        Bs[0][lc[i] + 2][lr[i]] = vb.z; Bs[0][lc[i] + 3][lr[i]] = vb.w;
    }
    __syncthreads();

#pragma unroll 1
    for (int kt = 0; kt < NT; kt++) {
        const int cur = kt & 1;
        float4 na[2], nb[2];
        const bool more = (kt + 1 < NT);
        if (more) {
            const int k0 = (kt + 1) << 4;
#pragma unroll
            for (int i = 0; i < 2; i++) {
                na[i] = *(const float4*)(A + (size_t)(m0 + lr[i]) * K + k0 + lc[i]);
                nb[i] = *(const float4*)(B + (size_t)(n0 + lr[i]) * K + k0 + lc[i]);
            }
        }
#pragma unroll
        for (int kk = 0; kk < 16; kk++) {
            float4 a0 = *(const float4*)&As[cur][kk][tr * 8];
            float4 a1 = *(const float4*)&As[cur][kk][tr * 8 + 4];
            ull b2[4];
#pragma unroll
            for (int j = 0; j < 4; j++)
                b2[j] = *(const ull*)&Bs[cur][kk][tc * 8 + 2 * j];
            ull ad[8];
            ad[0] = pack2(a0.x, a0.x); ad[1] = pack2(a0.y, a0.y);
            ad[2] = pack2(a0.z, a0.z); ad[3] = pack2(a0.w, a0.w);
            ad[4] = pack2(a1.x, a1.x); ad[5] = pack2(a1.y, a1.y);
            ad[6] = pack2(a1.z, a1.z); ad[7] = pack2(a1.w, a1.w);
#pragma unroll
            for (int i = 0; i < 8; i++)
#pragma unroll
                for (int j = 0; j < 4; j++)
                    ffma2(acc2[i][j], ad[i], b2[j]);
        }
        if (more) {
            const int nxt = cur ^ 1;
#pragma unroll
            for (int i = 0; i < 2; i++) {
                As[nxt][lc[i] + 0][lr[i]] = na[i].x; As[nxt][lc[i] + 1][lr[i]] = na[i].y;
                As[nxt][lc[i] + 2][lr[i]] = na[i].z; As[nxt][lc[i] + 3][lr[i]] = na[i].w;
                Bs[nxt][lc[i] + 0][lr[i]] = nb[i].x; Bs[nxt][lc[i] + 1][lr[i]] = nb[i].y;
                Bs[nxt][lc[i] + 2][lr[i]] = nb[i].z; Bs[nxt][lc[i] + 3][lr[i]] = nb[i].w;
            }
            __syncthreads();
        }
    }

#pragma unroll
    for (int i = 0; i < 8; i++) {
        int r = m0 + tr * 8 + i;
#pragma unroll
        for (int j = 0; j < 4; j++) {
            int c = n0 + tc * 8 + 2 * j;
            float x, y;
            unpack2(acc2[i][j], x, y);
            float2 v;
            v.x = alpha * (x + bias[c]);
            v.y = alpha * (y + bias[c + 1]);
            *(float2*)(C + (size_t)r * N + c) = v;
        }
    }
}

// ---------------- rel-pos bias expansion: biasF[h][q][k] -------------------
__global__ void __launch_bounds__(256) bias_pre(
    const float* __restrict__ btab_g, const int* __restrict__ rel,
    float* __restrict__ biasF)
{
    int idx = blockIdx.x * 256 + threadIdx.x;
    int ri  = rel[idx] * HEADS;
#pragma unroll
    for (int h = 0; h < HEADS; h++)
        biasF[h * (N1V * N2V) + idx] = btab_g[ri + h];
}

// ---------------- attention v4: register-tiled, 2 blocks/SM ----------------
// 256 threads; qg=tid>>4 (4 queries), kg=tid&15 (16 keys kj=16j+kg).
// smem: KV[256][36] | Pb[64][260]; Qs aliases the head of Pb (dead after QK).
#define SK 36
#define SQ 36
#define SP 260
#define KV_OFF 0
#define PB_OFF (256 * SK)                        // 9216 floats
#define ATTN_SMEM_FLOATS (PB_OFF + 64 * SP)      // 25856 floats
#define ATTN_SMEM_BYTES (ATTN_SMEM_FLOATS * 4)   // 103424 B -> 2 blocks/SM

__global__ void __launch_bounds__(256, 2) attn_kernel(
    const float* __restrict__ qh, const float* __restrict__ kvh,
    const float* __restrict__ mask, const float* __restrict__ biasF,
    float* __restrict__ xout)
{
    extern __shared__ float smem[];
    float* Ks = smem + KV_OFF;     // K tile, later V tile
    float* Pb = smem + PB_OFF;     // Qs alias, then mask+bias stage, then P
    float* Qs = Pb;

    const int tid = threadIdx.x;
    const int qg  = tid >> 4;
    const int kg  = tid & 15;
    const int q0  = blockIdx.x * 64;
    const int h   = blockIdx.y;
    const int b   = blockIdx.z;
    const int w   = b & (NWIN - 1);
    const int qi0 = qg * 4;

    // ---- load Q (64x32, into Pb head) and K (256x32) ----
    {
        const float* qbase = qh + ((size_t)(b * N1V + q0)) * DIM + h * HD;
#pragma unroll
        for (int i = 0; i < 2; i++) {
            int li = tid + i * 256;
            int r  = li >> 3;
            int c4 = (li & 7) * 4;
            *(float4*)&Qs[r * SQ + c4] =
                *(const float4*)(qbase + (size_t)r * DIM + c4);
        }
        const float* kbase = kvh + ((size_t)b * N2V) * (2 * DIM) + h * HD;
#pragma unroll
        for (int i = 0; i < 8; i++) {
            int li = tid + i * 256;
            int r  = li >> 3;
            int c4 = (li & 7) * 4;
            *(float4*)&Ks[r * SK + c4] =
                *(const float4*)(kbase + (size_t)r * (2 * DIM) + c4);
        }
    }
    __syncthreads();

    // ---- QK: s[4][16], 64 independent FMA chains ----
    float s[4][16];
#pragma unroll
    for (int i = 0; i < 4; i++)
#pragma unroll
        for (int j = 0; j < 16; j++) s[i][j] = 0.f;

#pragma unroll 2
    for (int c4 = 0; c4 < 8; c4++) {
        float q[4][4];
#pragma unroll
        for (int i = 0; i < 4; i++) {
            float4 v = *(const float4*)&Qs[(qi0 + i) * SQ + c4 * 4];
            q[i][0] = v.x; q[i][1] = v.y; q[i][2] = v.z; q[i][3] = v.w;
        }
#pragma unroll
        for (int j = 0; j < 16; j++) {
            float4 kv = *(const float4*)&Ks[(16 * j + kg) * SK + c4 * 4];
#pragma unroll
            for (int i = 0; i < 4; i++) {
                s[i][j] = fmaf(q[i][0], kv.x, s[i][j]);
                s[i][j] = fmaf(q[i][1], kv.y, s[i][j]);
                s[i][j] = fmaf(q[i][2], kv.z, s[i][j]);
                s[i][j] = fmaf(q[i][3], kv.w, s[i][j]);
            }
        }
    }
    __syncthreads();   // Q/K reads done -> V may overwrite Ks, stage may use Pb

    // ---- load V (over K) and mask+bias stage (into Pb) ----
    {
        const float* vbase = kvh + ((size_t)b * N2V) * (2 * DIM) + DIM + h * HD;
#pragma unroll
        for (int i = 0; i < 8; i++) {
            int li = tid + i * 256;
            int r  = li >> 3;
            int c4 = (li & 7) * 4;
            *(float4*)&Ks[r * SK + c4] =
                *(const float4*)(vbase + (size_t)r * (2 * DIM) + c4);
        }
        const float* maskb = mask  + ((size_t)(w * N1V + q0)) * N2V;
        const float* biasb = biasF + ((size_t)(h * N1V + q0)) * N2V;
#pragma unroll
        for (int i = 0; i < 16; i++) {
            int li = tid + i * 256;
            int r  = li >> 6;
            int c4 = (li & 63) * 4;
            float4 mv = *(const float4*)(maskb + (size_t)r * N2V + c4);
            float4 bv = *(const float4*)(biasb + (size_t)r * N2V + c4);
            float4 sv;
            sv.x = mv.x + bv.x; sv.y = mv.y + bv.y;
            sv.z = mv.z + bv.z; sv.w = mv.w + bv.w;
            *(float4*)&Pb[r * SP + c4] = sv;
        }
    }
    __syncthreads();

    // ---- add mask+bias; softmax via bfly over kg lane bits ----
#pragma unroll
    for (int i = 0; i < 4; i++)
#pragma unroll
        for (int j = 0; j < 16; j++)
            s[i][j] += Pb[(qi0 + i) * SP + 16 * j + kg];

    float linv[4];
#pragma unroll
    for (int i = 0; i < 4; i++) {
        float mx = s[i][0];
#pragma unroll
        for (int j = 1; j < 16; j++) mx = fmaxf(mx, s[i][j]);
        mx = fmaxf(mx, __shfl_xor_sync(0xFFFFFFFFu, mx, 1));
        mx = fmaxf(mx, __shfl_xor_sync(0xFFFFFFFFu, mx, 2));
        mx = fmaxf(mx, __shfl_xor_sync(0xFFFFFFFFu, mx, 4));
        mx = fmaxf(mx, __shfl_xor_sync(0xFFFFFFFFu, mx, 8));
        float ls = 0.f;
#pragma unroll
        for (int j = 0; j < 16; j++) {
            float e = __expf(s[i][j] - mx);
            s[i][j] = e;
            ls += e;
        }
        ls += __shfl_xor_sync(0xFFFFFFFFu, ls, 1);
        ls += __shfl_xor_sync(0xFFFFFFFFu, ls, 2);
        ls += __shfl_xor_sync(0xFFFFFFFFu, ls, 4);
        ls += __shfl_xor_sync(0xFFFFFFFFu, ls, 8);
        linv[i] = 1.0f / ls;
    }
    __syncthreads();   // stage reads done -> overwrite Pb with P

    // ---- store P (1/l folded) ----
#pragma unroll
    for (int i = 0; i < 4; i++)
#pragma unroll
        for (int j = 0; j < 16; j++)
            Pb[(qi0 + i) * SP + 16 * j + kg] = s[i][j] * linv[i];
    __syncthreads();

    // ---- PV: thread (qg, kg) -> 4 queries x dims {2kg, 2kg+1} ----
    float o[4][2];
#pragma unroll
    for (int i = 0; i < 4; i++) { o[i][0] = 0.f; o[i][1] = 0.f; }

#pragma unroll 4
    for (int k4 = 0; k4 < 64; k4++) {
        float p[4][4];
#pragma unroll
        for (int i = 0; i < 4; i++) {
            float4 v = *(const float4*)&Pb[(qi0 + i) * SP + k4 * 4];
            p[i][0] = v.x; p[i][1] = v.y; p[i][2] = v.z; p[i][3] = v.w;
        }
#pragma unroll
        for (int kk = 0; kk < 4; kk++) {
            float2 vv = *(const float2*)&Ks[(k4 * 4 + kk) * SK + 2 * kg];
#pragma unroll
            for (int i = 0; i < 4; i++) {
                o[i][0] = fmaf(p[i][kk], vv.x, o[i][0]);
                o[i][1] = fmaf(p[i][kk], vv.y, o[i][1]);
            }
        }
    }

    // ---- write O ----
#pragma unroll
    for (int i = 0; i < 4; i++) {
        float2 v; v.x = o[i][0]; v.y = o[i][1];
        *(float2*)(xout + ((size_t)(b * N1V + q0 + qi0 + i)) * DIM
                   + h * HD + 2 * kg) = v;
    }
}

// ---------------- launch ----------------
extern "C" void kernel_launch(void* const* d_in, const int* in_sizes, int n_in,
                              void* d_out, int out_size)
{
    const float* q    = (const float*)d_in[0];
    const float* kv   = (const float*)d_in[1];
    const float* mask = (const float*)d_in[2];
    const float* Wq   = (const float*)d_in[3];
    const float* bq   = (const float*)d_in[4];
    const float* Wkv  = (const float*)d_in[5];
    const float* bkv  = (const float*)d_in[6];
    const float* btab = (const float*)d_in[7];
    const float* Wp   = (const float*)d_in[8];
    const float* bp   = (const float*)d_in[9];
    const int*   rel  = (const int*)d_in[10];
    float* out = (float*)d_out;

    static float* qh  = nullptr;
    static float* kvh = nullptr;
    static float* xb  = nullptr;
    static float* bF  = nullptr;
    if (!qh) {
        cudaGetSymbolAddress((void**)&qh,  d_qh);
        cudaGetSymbolAddress((void**)&kvh, d_kvh);
        cudaGetSymbolAddress((void**)&xb,  d_x);
        cudaGetSymbolAddress((void**)&bF,  d_biasF);
        cudaFuncSetAttribute(attn_kernel,
                             cudaFuncAttributeMaxDynamicSharedMemorySize,
                             ATTN_SMEM_BYTES);
    }

    const int M = MTOT;
    const float scale = 0.17677669529663687f;       // 1/sqrt(32)

    bias_pre<<<N1V * N2V / 256, 256>>>(btab, rel, bF);
    gemm_nt<<<dim3(DIM / 128, M / 128), 256>>>(q, Wq, bq, qh, M, DIM, DIM, scale);
    gemm_nt<<<dim3((2 * DIM) / 128, M / 128), 256>>>(kv, Wkv, bkv, kvh, M, 2 * DIM, DIM, 1.f);
    attn_kernel<<<dim3(4, HEADS, BTOT), 256, ATTN_SMEM_BYTES>>>(qh, kvh, mask, bF, xb);
    gemm_nt<<<dim3(DIM / 128, M / 128), 256>>>(xb, Wp, bp, out, M, DIM, DIM, 1.f);
}